// round 12
// baseline (speedup 1.0000x reference)
#include <cuda_runtime.h>
#include <cuda_bf16.h>
#include <math.h>
#include <stdint.h>

// ---------------- static scratch (device globals; no allocation allowed) -----
#define MAXN   50048
#define MAXE   800000
#define MAXEA  (MAXE + MAXN)
#define HD     256        // H*HID
#define FD     64
#define MAXG   1024
#define SCAP   96         // smem bucket-sort capacity per node
#define MAXBLK 6256       // ceil(MAXN/8) gat blocks

__device__ int   g_deg[MAXN];         // zero-init at load; re-zeroed by k_place
__device__ int   g_cursor[MAXN];
__device__ int   g_rowptr[MAXN + 1];
__device__ int   g_sidx[MAXEA];
__device__ int   g_ssrc[MAXEA];
__device__ __nv_bfloat162 g_xlh[(size_t)MAXN * (HD / 2)];   // xl in bf16
__device__ float g_xr[(size_t)MAXN * HD];
__device__ float g_gat[(size_t)MAXN * FD];
__device__ float g_h[(size_t)MAXN * FD];
__device__ float g_ps2[(size_t)MAXBLK * FD];
__device__ float g_pq2[(size_t)MAXBLK * FD];
__device__ float g_bna[FD];
__device__ float g_bnb[FD];
__device__ int   g_gstart[MAXG + 1];
__device__ float g_pool[(size_t)MAXG * FD];

// ---------------- deterministic CSR build: bucket + per-bucket sort ---------
__global__ void k_deg(const int* __restrict__ edst, int E, int EA) {
    int i = blockIdx.x * blockDim.x + threadIdx.x;
    if (i >= EA) return;
    int d = (i < E) ? edst[i] : (i - E);       // self loops appended
    atomicAdd(&g_deg[d], 1);
}

__global__ void k_scan(int N, int EA) {
    __shared__ int sm[1024];
    int t = threadIdx.x;
    int chunk = (N + 1023) / 1024;
    int s = t * chunk, e = min(s + chunk, N);
    int sum = 0;
    for (int i = s; i < e; i++) sum += g_deg[i];
    sm[t] = sum;
    __syncthreads();
    for (int off = 1; off < 1024; off <<= 1) {
        int v = (t >= off) ? sm[t - off] : 0;
        __syncthreads();
        sm[t] += v;
        __syncthreads();
    }
    int base = sm[t] - sum;   // exclusive prefix
    for (int i = s; i < e; i++) {
        g_rowptr[i] = base;
        g_cursor[i] = base;
        base += g_deg[i];
    }
    if (t == 0) g_rowptr[N] = EA;
}

__global__ void k_place(const int* __restrict__ edst, int E, int EA, int N) {
    int i = blockIdx.x * blockDim.x + threadIdx.x;
    if (i < N) g_deg[i] = 0;     // reset for the next kernel_launch call
    if (i >= EA) return;
    int d = (i < E) ? edst[i] : (i - E);
    int pos = atomicAdd(&g_cursor[d], 1);
    g_sidx[pos] = i;             // store original edge index (unique key)
}

// thread per node: sort its bucket by original edge index -> deterministic
__global__ void k_sortbuckets(const int* __restrict__ esrc, int E, int N) {
    __shared__ int buf[SCAP * 128];
    int tid = threadIdx.x;                    // 128 threads
    int node = blockIdx.x * 128 + tid;
    if (node >= N) return;
    int e0 = g_rowptr[node], e1 = g_rowptr[node + 1];
    int deg = e1 - e0;
    if (deg <= SCAP) {
        for (int j = 0; j < deg; j++) buf[j * 128 + tid] = g_sidx[e0 + j];
        for (int a = 1; a < deg; a++) {
            int v = buf[a * 128 + tid];
            int j = a - 1;
            while (j >= 0 && buf[j * 128 + tid] > v) {
                buf[(j + 1) * 128 + tid] = buf[j * 128 + tid];
                j--;
            }
            buf[(j + 1) * 128 + tid] = v;
        }
        for (int j = 0; j < deg; j++) {
            int v = buf[j * 128 + tid];
            g_ssrc[e0 + j] = (v < E) ? esrc[v] : (v - E);
        }
    } else {
        int* b = g_sidx + e0;                 // rare fallback: global in-place
        for (int a = 1; a < deg; a++) {
            int v = b[a];
            int j = a - 1;
            while (j >= 0 && b[j] > v) { b[j + 1] = b[j]; j--; }
            b[j + 1] = v;
        }
        for (int j = 0; j < deg; j++) {
            int v = b[j];
            g_ssrc[e0 + j] = (v < E) ? esrc[v] : (v - E);
        }
    }
}

// ---------------- TF32 tensor-core GEMM: C[N,256] = A[N,64] @ W[64,256] -----
// xl half of the output is stored as bf16 (for the GAT gather); xr half fp32.
__device__ __forceinline__ uint32_t f2tf(float f) {
    uint32_t u;
    asm("cvt.rna.tf32.f32 %0, %1;" : "=r"(u) : "f"(f));
    return u;
}
__device__ __forceinline__ void mma_tf32(float* c, const uint32_t* a, const uint32_t* b) {
    asm volatile("mma.sync.aligned.m16n8k8.row.col.f32.tf32.tf32.f32 "
                 "{%0,%1,%2,%3}, {%4,%5,%6,%7}, {%8,%9}, {%0,%1,%2,%3};"
                 : "+f"(c[0]), "+f"(c[1]), "+f"(c[2]), "+f"(c[3])
                 : "r"(a[0]), "r"(a[1]), "r"(a[2]), "r"(a[3]),
                   "r"(b[0]), "r"(b[1]));
}
// XOR swizzles (conflict-free fragment loads, 16B-aligned fills preserved)
#define ASW(r, c) ((c) ^ (((r) & 7) << 2))
#define BSW(k, n) ((n) ^ (((k) & 3) << 3))

// tile 128 rows x 64 cols, 256 threads (8 warps = 4x2 of 32x32 warptiles)
__global__ void k_gemm(const float* __restrict__ A, const float* __restrict__ Wl,
                       const float* __restrict__ Wr, int N) {
    __shared__ uint32_t As[128][64];   // 32KB, tf32
    __shared__ uint32_t Bs[64][64];    // 16KB, tf32
    int tid = threadIdx.x;
    int wid = tid >> 5, lane = tid & 31;
    int m0 = blockIdx.x * 128;
    int cb = blockIdx.y * 64;
    bool is_xl = (cb < 256);
    const float* W = is_xl ? Wl : Wr;
    int c0 = is_xl ? cb : cb - 256;

    const float4* A4 = (const float4*)A;
#pragma unroll
    for (int q = 0; q < 8; q++) {             // 2048 float4
        int fi = q * 256 + tid;
        int r = fi >> 4, c4 = fi & 15;
        float4 v = make_float4(0.f, 0.f, 0.f, 0.f);
        if (m0 + r < N) v = A4[(size_t)(m0 + r) * 16 + c4];
        uint4 u = make_uint4(f2tf(v.x), f2tf(v.y), f2tf(v.z), f2tf(v.w));
        *(uint4*)&As[r][ASW(r, c4 * 4)] = u;
    }
    const float4* W4 = (const float4*)W;      // W is [64,256]: 64 float4/row
#pragma unroll
    for (int q = 0; q < 4; q++) {             // 1024 float4
        int fi = q * 256 + tid;
        int k = fi >> 4, n4 = fi & 15;
        float4 v = W4[(size_t)k * 64 + (c0 >> 2) + n4];
        uint4 u = make_uint4(f2tf(v.x), f2tf(v.y), f2tf(v.z), f2tf(v.w));
        *(uint4*)&Bs[k][BSW(k, n4 * 4)] = u;
    }
    __syncthreads();

    int wm = (wid & 3) * 32, wn = (wid >> 2) * 32;
    int ar = lane >> 2, ac = lane & 3;
    float acc[2][4][4];
#pragma unroll
    for (int mi = 0; mi < 2; mi++)
#pragma unroll
        for (int ni = 0; ni < 4; ni++)
#pragma unroll
            for (int c = 0; c < 4; c++) acc[mi][ni][c] = 0.f;

#pragma unroll
    for (int ks = 0; ks < 8; ks++) {
        uint32_t a[2][4], b[4][2];
#pragma unroll
        for (int mi = 0; mi < 2; mi++) {
            int r0 = wm + mi * 16 + ar, r1 = r0 + 8;
            int cA = ks * 8 + ac;
            a[mi][0] = As[r0][ASW(r0, cA)];
            a[mi][1] = As[r1][ASW(r1, cA)];
            a[mi][2] = As[r0][ASW(r0, cA + 4)];
            a[mi][3] = As[r1][ASW(r1, cA + 4)];
        }
#pragma unroll
        for (int ni = 0; ni < 4; ni++) {
            int nn = wn + ni * 8 + ar;
            int k0 = ks * 8 + ac, k1 = k0 + 4;
            b[ni][0] = Bs[k0][BSW(k0, nn)];
            b[ni][1] = Bs[k1][BSW(k1, nn)];
        }
#pragma unroll
        for (int mi = 0; mi < 2; mi++)
#pragma unroll
            for (int ni = 0; ni < 4; ni++)
                mma_tf32(acc[mi][ni], a[mi], b[ni]);
    }
    // epilogue: rows < MAXN always (391*128 = 50048 = MAXN), no guard needed
    if (is_xl) {
#pragma unroll
        for (int mi = 0; mi < 2; mi++) {
            int r = m0 + wm + mi * 16 + ar;
#pragma unroll
            for (int ni = 0; ni < 4; ni++) {
                int c = c0 + wn + ni * 8 + ac * 2;   // even col; pair (c, c+1)
                g_xlh[(size_t)r * 128 + (c >> 1)] =
                    __floats2bfloat162_rn(acc[mi][ni][0], acc[mi][ni][1]);
                g_xlh[(size_t)(r + 8) * 128 + (c >> 1)] =
                    __floats2bfloat162_rn(acc[mi][ni][2], acc[mi][ni][3]);
            }
        }
    } else {
#pragma unroll
        for (int mi = 0; mi < 2; mi++) {
            int r = m0 + wm + mi * 16 + ar;
#pragma unroll
            for (int ni = 0; ni < 4; ni++) {
                int c = c0 + wn + ni * 8 + ac * 2;
                *(float2*)&g_xr[(size_t)r * 256 + c] =
                    make_float2(acc[mi][ni][0], acc[mi][ni][1]);
                *(float2*)&g_xr[(size_t)(r + 8) * 256 + c] =
                    make_float2(acc[mi][ni][2], acc[mi][ni][3]);
            }
        }
    }
}

// ---------------- GATv2: warp per dst node + fused BN partial stats ---------
// lane l owns flat indices [8l, 8l+8) of [H=4, C=64]; head = l>>3
__device__ __forceinline__ void unpack8(uint4 q, float* f) {
    __nv_bfloat162 h0 = *(__nv_bfloat162*)&q.x;
    __nv_bfloat162 h1 = *(__nv_bfloat162*)&q.y;
    __nv_bfloat162 h2 = *(__nv_bfloat162*)&q.z;
    __nv_bfloat162 h3 = *(__nv_bfloat162*)&q.w;
    f[0] = __bfloat162float(h0.x); f[1] = __bfloat162float(h0.y);
    f[2] = __bfloat162float(h1.x); f[3] = __bfloat162float(h1.y);
    f[4] = __bfloat162float(h2.x); f[5] = __bfloat162float(h2.y);
    f[6] = __bfloat162float(h3.x); f[7] = __bfloat162float(h3.y);
}

__global__ void k_gat(const float* __restrict__ att, const float* __restrict__ bias, int N) {
    __shared__ float ssum[8][64];
    __shared__ float ssq[8][64];
    int w = threadIdx.x >> 5;
    int lane = threadIdx.x & 31;
    int node = blockIdx.x * 8 + w;
    bool valid = node < N;
    int nidx = valid ? node : 0;
    const uint4* xlh = (const uint4*)g_xlh;   // row = 32 uint4
    const float4* xr4 = (const float4*)g_xr;

    float4 r0 = xr4[(size_t)nidx * 64 + lane * 2];
    float4 r1 = xr4[(size_t)nidx * 64 + lane * 2 + 1];
    float rr[8] = {r0.x, r0.y, r0.z, r0.w, r1.x, r1.y, r1.z, r1.w};
    float4 a0 = ((const float4*)att)[lane * 2];
    float4 a1 = ((const float4*)att)[lane * 2 + 1];
    float at[8] = {a0.x, a0.y, a0.z, a0.w, a1.x, a1.y, a1.z, a1.w};

    float m = -1e30f, s = 0.f;
    float acc[8] = {0.f, 0.f, 0.f, 0.f, 0.f, 0.f, 0.f, 0.f};
    int e0 = valid ? g_rowptr[node] : 0;
    int e1 = valid ? g_rowptr[node + 1] : 0;
    int e = e0;
    for (; e + 2 <= e1; e += 2) {             // 2-edge unroll
        int j0 = g_ssrc[e], j1 = g_ssrc[e + 1];
        uint4 q0 = xlh[(size_t)j0 * 32 + lane];
        uint4 q1 = xlh[(size_t)j1 * 32 + lane];
        float f0[8], f1[8];
        unpack8(q0, f0);
        unpack8(q1, f1);
        float p0 = 0.f, p1 = 0.f;
#pragma unroll
        for (int k = 0; k < 8; k++) {
            float t0 = f0[k] + rr[k];
            float t1 = f1[k] + rr[k];
            t0 = (t0 > 0.f) ? t0 : 0.2f * t0;
            t1 = (t1 > 0.f) ? t1 : 0.2f * t1;
            p0 += at[k] * t0;
            p1 += at[k] * t1;
        }
        p0 += __shfl_xor_sync(0xffffffffu, p0, 1);
        p1 += __shfl_xor_sync(0xffffffffu, p1, 1);
        p0 += __shfl_xor_sync(0xffffffffu, p0, 2);
        p1 += __shfl_xor_sync(0xffffffffu, p1, 2);
        p0 += __shfl_xor_sync(0xffffffffu, p0, 4);
        p1 += __shfl_xor_sync(0xffffffffu, p1, 4);
        float mn = fmaxf(m, fmaxf(p0, p1));
        float sc = __expf(m - mn);
        float w0 = __expf(p0 - mn);
        float w1 = __expf(p1 - mn);
        s = s * sc + w0 + w1;
#pragma unroll
        for (int k = 0; k < 8; k++)
            acc[k] = acc[k] * sc + w0 * f0[k] + w1 * f1[k];
        m = mn;
    }
    if (e < e1) {                             // tail (0 or 1 edge)
        int j = g_ssrc[e];
        uint4 q = xlh[(size_t)j * 32 + lane];
        float f[8];
        unpack8(q, f);
        float p = 0.f;
#pragma unroll
        for (int k = 0; k < 8; k++) {
            float t = f[k] + rr[k];
            t = (t > 0.f) ? t : 0.2f * t;
            p += at[k] * t;
        }
        p += __shfl_xor_sync(0xffffffffu, p, 1);
        p += __shfl_xor_sync(0xffffffffu, p, 2);
        p += __shfl_xor_sync(0xffffffffu, p, 4);
        float mn = fmaxf(m, p);
        float sc = __expf(m - mn);
        float ww = __expf(p - mn);
        s = s * sc + ww;
#pragma unroll
        for (int k = 0; k < 8; k++) acc[k] = acc[k] * sc + ww * f[k];
        m = mn;
    }
    float inv = 1.0f / s;
#pragma unroll
    for (int k = 0; k < 8; k++) {
        float v = acc[k] * inv;                    // per-head normalized
        v += __shfl_xor_sync(0xffffffffu, v, 8);   // sum over 4 heads
        v += __shfl_xor_sync(0xffffffffu, v, 16);
        acc[k] = v;
    }
    if (lane < 8) {
        float4 b0 = ((const float4*)bias)[lane * 2];
        float4 b1 = ((const float4*)bias)[lane * 2 + 1];
        float bv[8] = {b0.x, b0.y, b0.z, b0.w, b1.x, b1.y, b1.z, b1.w};
        float o[8];
#pragma unroll
        for (int k = 0; k < 8; k++) {
            o[k] = valid ? (0.25f * acc[k] + bv[k]) : 0.f;
            ssum[w][lane * 8 + k] = o[k];
            ssq[w][lane * 8 + k] = o[k] * o[k];
        }
        if (valid) {
            float4 w0 = make_float4(o[0], o[1], o[2], o[3]);
            float4 w1 = make_float4(o[4], o[5], o[6], o[7]);
            ((float4*)g_gat)[(size_t)node * 16 + lane * 2]     = w0;
            ((float4*)g_gat)[(size_t)node * 16 + lane * 2 + 1] = w1;
        }
    }
    __syncthreads();
    if (threadIdx.x < 64) {                   // per-block BN partials (fixed order)
        float s2 = 0.f, q2 = 0.f;
#pragma unroll
        for (int ww = 0; ww < 8; ww++) {
            s2 += ssum[ww][threadIdx.x];
            q2 += ssq[ww][threadIdx.x];
        }
        g_ps2[(size_t)blockIdx.x * 64 + threadIdx.x] = s2;
        g_pq2[(size_t)blockIdx.x * 64 + threadIdx.x] = q2;
    }
}

// ---------------- BN finalize: one block per channel, deterministic ---------
__global__ void k_bnfin2(const float* __restrict__ gamma, const float* __restrict__ beta,
                         int N, int nblk) {
    __shared__ float S[256], Q[256];
    int c = blockIdx.x;                       // 64 blocks
    int t = threadIdx.x;                      // 256 threads
    float s = 0.f, q = 0.f;
    for (int b = t; b < nblk; b += 256) {     // fixed per-thread stride order
        s += g_ps2[(size_t)b * 64 + c];
        q += g_pq2[(size_t)b * 64 + c];
    }
    S[t] = s; Q[t] = q;
    __syncthreads();
    for (int off = 128; off > 0; off >>= 1) { // fixed tree order
        if (t < off) { S[t] += S[t + off]; Q[t] += Q[t + off]; }
        __syncthreads();
    }
    if (t == 0) {
        float mu = S[0] / (float)N;
        float var = Q[0] / (float)N - mu * mu;
        float iv = rsqrtf(var + 1e-5f);
        float a = gamma[c] * iv;
        g_bna[c] = a;
        g_bnb[c] = beta[c] - a * mu;
    }
}

__global__ void k_bngelu(int total, int residual) {
    int i = blockIdx.x * blockDim.x + threadIdx.x;
    if (i >= total) return;
    int c = i & 63;
    float t = g_bna[c] * g_gat[i] + g_bnb[c];
    float ge = 0.5f * t * (1.0f + erff(t * 0.70710678118654752f));
    g_h[i] = residual ? (ge + g_h[i]) : ge;
}

// ---------------- pooling + heads -------------------------------------------
__global__ void k_bounds(const int* __restrict__ batch, int N, int G) {
    int i = blockIdx.x * blockDim.x + threadIdx.x;
    if (i >= N) return;
    int b = batch[i];
    int prev = (i == 0) ? -1 : batch[i - 1];
    for (int g = prev + 1; g <= b; g++) g_gstart[g] = i;
    if (i == N - 1) for (int g = b + 1; g <= G; g++) g_gstart[g] = N;
}

__global__ void k_pool(int G) {
    int g = blockIdx.x, c = threadIdx.x;   // 64 threads
    float s = 0.f;
    int e = g_gstart[g + 1];
    for (int n = g_gstart[g]; n < e; n++) s += g_h[(size_t)n * 64 + c];
    g_pool[(size_t)g * 64 + c] = s;
}

__global__ void k_heads(const float* __restrict__ Wmu, const float* __restrict__ bmu,
                        const float* __restrict__ Wlv, const float* __restrict__ blv,
                        float* __restrict__ out, int G) {
    int g = blockIdx.x, t = threadIdx.x;   // 128 threads
    __shared__ float p[64];
    if (t < 64) p[t] = g_pool[(size_t)g * 64 + t];
    __syncthreads();
    int c = t & 63;
    const float* W = (t < 64) ? Wmu : Wlv;
    float s = (t < 64) ? bmu[c] : blv[c];
    for (int k = 0; k < 64; k++) s += p[k] * W[k * 64 + c];
    out[((t < 64) ? 0 : (size_t)G * 64) + (size_t)g * 64 + c] = s;
}

// ---------------- host orchestration ----------------------------------------
extern "C" void kernel_launch(void* const* d_in, const int* in_sizes, int n_in,
                              void* d_out, int out_size) {
    // metadata: x, edge_src, edge_dst, batch, [num_graphs],
    //           (Wl,Wr,att,b,g,be) x3, Wmu, bmu, Wlv, blv
    bool has_ng = (n_in >= 27);
    auto IX = [&](int i) { return has_ng ? i : (i > 4 ? i - 1 : i); };

    const float* x     = (const float*)d_in[0];
    const int*   esrc  = (const int*)d_in[1];
    const int*   edst  = (const int*)d_in[2];
    const int*   batch = (const int*)d_in[3];

    int N  = in_sizes[0] / 64;
    int E  = in_sizes[1];
    int EA = E + N;
    int G  = out_size / 128;   // 2 * G * 64

    void* hptr_v = nullptr;
    cudaGetSymbolAddress(&hptr_v, g_h);
    const float* hbuf = (const float*)hptr_v;

    // ---- deterministic CSR: bucket scatter + per-bucket index sort ----
    // (g_deg zeroed statically at load; k_place re-zeroes it for the next call)
    k_deg        <<<(EA + 255) / 256, 256>>>(edst, E, EA);
    k_scan       <<<1, 1024>>>(N, EA);
    k_place      <<<(EA + 255) / 256, 256>>>(edst, E, EA, N);
    k_sortbuckets<<<(N + 127) / 128, 128>>>(esrc, E, N);

    // ---- 3 GATv2 layers ----
    int gatblk = (N + 7) / 8;
    const float* hin = x;
    for (int L = 0; L < 3; L++) {
        int b0 = 5 + 6 * L;
        const float* Wl  = (const float*)d_in[IX(b0 + 0)];
        const float* Wr  = (const float*)d_in[IX(b0 + 1)];
        const float* att = (const float*)d_in[IX(b0 + 2)];
        const float* bb  = (const float*)d_in[IX(b0 + 3)];
        const float* gg  = (const float*)d_in[IX(b0 + 4)];
        const float* be  = (const float*)d_in[IX(b0 + 5)];

        dim3 gg_gemm((N + 127) / 128, 8);
        k_gemm  <<<gg_gemm, 256>>>(hin, Wl, Wr, N);
        k_gat   <<<gatblk, 256>>>(att, bb, N);
        k_bnfin2<<<64, 256>>>(gg, be, N, gatblk);
        k_bngelu<<<(N * 64 + 255) / 256, 256>>>(N * 64, (L > 0) ? 1 : 0);
        hin = hbuf;
    }

    // ---- pool + heads ----
    const float* Wmu = (const float*)d_in[IX(23)];
    const float* bmu = (const float*)d_in[IX(24)];
    const float* Wlv = (const float*)d_in[IX(25)];
    const float* blv = (const float*)d_in[IX(26)];

    k_bounds<<<(N + 255) / 256, 256>>>(batch, N, G);
    k_pool  <<<G, 64>>>(G);
    k_heads <<<G, 128>>>(Wmu, bmu, Wlv, blv, (float*)d_out, G);
}

// round 13
// speedup vs baseline: 1.4396x; 1.4396x over previous
#include <cuda_runtime.h>
#include <cuda_bf16.h>
#include <math.h>
#include <stdint.h>

// ---------------- static scratch (device globals; no allocation allowed) -----
#define MAXN   50048
#define MAXE   800000
#define MAXEA  (MAXE + MAXN)
#define HD     256        // H*HID
#define FD     64
#define MAXG   1024
#define SCAP   96         // smem bucket-sort capacity per node

__device__ int   g_deg[MAXN];         // zero at load; re-zeroed by k_place each run
__device__ int   g_cursor[MAXN];
__device__ int   g_rowptr[MAXN + 1];
__device__ int   g_sidx[MAXEA];
__device__ int   g_ssrc[MAXEA];
__device__ __nv_bfloat162 g_xlh[(size_t)MAXN * (HD / 2)];   // xl in bf16
__device__ float g_xr[(size_t)MAXN * HD];
__device__ float g_gat[(size_t)MAXN * FD];
__device__ float g_h[(size_t)MAXN * FD];
__device__ float g_psum[256 * FD];
__device__ float g_psq[256 * FD];
__device__ float g_bna[FD];
__device__ float g_bnb[FD];
__device__ int   g_gstart[MAXG + 1];
__device__ float g_pool[(size_t)MAXG * FD];

// ---------------- deterministic CSR build: bucket + per-bucket sort ---------
__global__ void k_deg(const int* __restrict__ edst, int E, int EA) {
    int i = blockIdx.x * blockDim.x + threadIdx.x;
    if (i >= EA) return;
    int d = (i < E) ? edst[i] : (i - E);       // self loops appended
    atomicAdd(&g_deg[d], 1);
}

__global__ void k_scan(int N, int EA) {
    __shared__ int sm[1024];
    int t = threadIdx.x;
    int chunk = (N + 1023) / 1024;
    int s = t * chunk, e = min(s + chunk, N);
    int sum = 0;
    for (int i = s; i < e; i++) sum += g_deg[i];
    sm[t] = sum;
    __syncthreads();
    for (int off = 1; off < 1024; off <<= 1) {
        int v = (t >= off) ? sm[t - off] : 0;
        __syncthreads();
        sm[t] += v;
        __syncthreads();
    }
    int base = sm[t] - sum;   // exclusive prefix
    for (int i = s; i < e; i++) {
        g_rowptr[i] = base;
        g_cursor[i] = base;
        base += g_deg[i];
    }
    if (t == 0) g_rowptr[N] = EA;
}

__global__ void k_place(const int* __restrict__ edst, int E, int EA, int N) {
    int i = blockIdx.x * blockDim.x + threadIdx.x;
    if (i < N) g_deg[i] = 0;     // g_deg dead after k_scan; reset for next run
    if (i >= EA) return;
    int d = (i < E) ? edst[i] : (i - E);
    int pos = atomicAdd(&g_cursor[d], 1);
    g_sidx[pos] = i;             // store original edge index (unique key)
}

// thread per node: sort its bucket by original edge index -> deterministic
__global__ void k_sortbuckets(const int* __restrict__ esrc, int E, int N) {
    __shared__ int buf[SCAP * 128];
    int tid = threadIdx.x;                    // 128 threads
    int node = blockIdx.x * 128 + tid;
    if (node >= N) return;
    int e0 = g_rowptr[node], e1 = g_rowptr[node + 1];
    int deg = e1 - e0;
    if (deg <= SCAP) {
        for (int j = 0; j < deg; j++) buf[j * 128 + tid] = g_sidx[e0 + j];
        for (int a = 1; a < deg; a++) {
            int v = buf[a * 128 + tid];
            int j = a - 1;
            while (j >= 0 && buf[j * 128 + tid] > v) {
                buf[(j + 1) * 128 + tid] = buf[j * 128 + tid];
                j--;
            }
            buf[(j + 1) * 128 + tid] = v;
        }
        for (int j = 0; j < deg; j++) {
            int v = buf[j * 128 + tid];
            g_ssrc[e0 + j] = (v < E) ? esrc[v] : (v - E);
        }
    } else {
        int* b = g_sidx + e0;                 // rare fallback: global in-place
        for (int a = 1; a < deg; a++) {
            int v = b[a];
            int j = a - 1;
            while (j >= 0 && b[j] > v) { b[j + 1] = b[j]; j--; }
            b[j + 1] = v;
        }
        for (int j = 0; j < deg; j++) {
            int v = b[j];
            g_ssrc[e0 + j] = (v < E) ? esrc[v] : (v - E);
        }
    }
}

// ---------------- TF32 tensor-core GEMM: C[N,256] = A[N,64] @ W[64,256] -----
// xl half of the output is stored as bf16 (for the GAT gather); xr half fp32.
__device__ __forceinline__ uint32_t f2tf(float f) {
    uint32_t u;
    asm("cvt.rna.tf32.f32 %0, %1;" : "=r"(u) : "f"(f));
    return u;
}
__device__ __forceinline__ void mma_tf32(float* c, const uint32_t* a, const uint32_t* b) {
    asm volatile("mma.sync.aligned.m16n8k8.row.col.f32.tf32.tf32.f32 "
                 "{%0,%1,%2,%3}, {%4,%5,%6,%7}, {%8,%9}, {%0,%1,%2,%3};"
                 : "+f"(c[0]), "+f"(c[1]), "+f"(c[2]), "+f"(c[3])
                 : "r"(a[0]), "r"(a[1]), "r"(a[2]), "r"(a[3]),
                   "r"(b[0]), "r"(b[1]));
}
// XOR swizzles (conflict-free fragment loads, 16B-aligned fills preserved)
#define ASW(r, c) ((c) ^ (((r) & 7) << 2))
#define BSW(k, n) ((n) ^ (((k) & 3) << 3))

// tile 128 rows x 64 cols, 256 threads (8 warps = 4x2 of 32x32 warptiles)
__global__ void k_gemm(const float* __restrict__ A, const float* __restrict__ Wl,
                       const float* __restrict__ Wr, int N) {
    __shared__ uint32_t As[128][64];   // 32KB, tf32
    __shared__ uint32_t Bs[64][64];    // 16KB, tf32
    int tid = threadIdx.x;
    int wid = tid >> 5, lane = tid & 31;
    int m0 = blockIdx.x * 128;
    int cb = blockIdx.y * 64;
    bool is_xl = (cb < 256);
    const float* W = is_xl ? Wl : Wr;
    int c0 = is_xl ? cb : cb - 256;

    const float4* A4 = (const float4*)A;
#pragma unroll
    for (int q = 0; q < 8; q++) {             // 2048 float4
        int fi = q * 256 + tid;
        int r = fi >> 4, c4 = fi & 15;
        float4 v = make_float4(0.f, 0.f, 0.f, 0.f);
        if (m0 + r < N) v = A4[(size_t)(m0 + r) * 16 + c4];
        uint4 u = make_uint4(f2tf(v.x), f2tf(v.y), f2tf(v.z), f2tf(v.w));
        *(uint4*)&As[r][ASW(r, c4 * 4)] = u;
    }
    const float4* W4 = (const float4*)W;      // W is [64,256]: 64 float4/row
#pragma unroll
    for (int q = 0; q < 4; q++) {             // 1024 float4
        int fi = q * 256 + tid;
        int k = fi >> 4, n4 = fi & 15;
        float4 v = W4[(size_t)k * 64 + (c0 >> 2) + n4];
        uint4 u = make_uint4(f2tf(v.x), f2tf(v.y), f2tf(v.z), f2tf(v.w));
        *(uint4*)&Bs[k][BSW(k, n4 * 4)] = u;
    }
    __syncthreads();

    int wm = (wid & 3) * 32, wn = (wid >> 2) * 32;
    int ar = lane >> 2, ac = lane & 3;
    float acc[2][4][4];
#pragma unroll
    for (int mi = 0; mi < 2; mi++)
#pragma unroll
        for (int ni = 0; ni < 4; ni++)
#pragma unroll
            for (int c = 0; c < 4; c++) acc[mi][ni][c] = 0.f;

#pragma unroll
    for (int ks = 0; ks < 8; ks++) {
        uint32_t a[2][4], b[4][2];
#pragma unroll
        for (int mi = 0; mi < 2; mi++) {
            int r0 = wm + mi * 16 + ar, r1 = r0 + 8;
            int cA = ks * 8 + ac;
            a[mi][0] = As[r0][ASW(r0, cA)];
            a[mi][1] = As[r1][ASW(r1, cA)];
            a[mi][2] = As[r0][ASW(r0, cA + 4)];
            a[mi][3] = As[r1][ASW(r1, cA + 4)];
        }
#pragma unroll
        for (int ni = 0; ni < 4; ni++) {
            int nn = wn + ni * 8 + ar;
            int k0 = ks * 8 + ac, k1 = k0 + 4;
            b[ni][0] = Bs[k0][BSW(k0, nn)];
            b[ni][1] = Bs[k1][BSW(k1, nn)];
        }
#pragma unroll
        for (int mi = 0; mi < 2; mi++)
#pragma unroll
            for (int ni = 0; ni < 4; ni++)
                mma_tf32(acc[mi][ni], a[mi], b[ni]);
    }
    // epilogue: rows < MAXN always (391*128 = 50048 = MAXN), no guard needed
    if (is_xl) {
#pragma unroll
        for (int mi = 0; mi < 2; mi++) {
            int r = m0 + wm + mi * 16 + ar;
#pragma unroll
            for (int ni = 0; ni < 4; ni++) {
                int c = c0 + wn + ni * 8 + ac * 2;   // even col; pair (c, c+1)
                g_xlh[(size_t)r * 128 + (c >> 1)] =
                    __floats2bfloat162_rn(acc[mi][ni][0], acc[mi][ni][1]);
                g_xlh[(size_t)(r + 8) * 128 + (c >> 1)] =
                    __floats2bfloat162_rn(acc[mi][ni][2], acc[mi][ni][3]);
            }
        }
    } else {
#pragma unroll
        for (int mi = 0; mi < 2; mi++) {
            int r = m0 + wm + mi * 16 + ar;
#pragma unroll
            for (int ni = 0; ni < 4; ni++) {
                int c = c0 + wn + ni * 8 + ac * 2;
                *(float2*)&g_xr[(size_t)r * 256 + c] =
                    make_float2(acc[mi][ni][0], acc[mi][ni][1]);
                *(float2*)&g_xr[(size_t)(r + 8) * 256 + c] =
                    make_float2(acc[mi][ni][2], acc[mi][ni][3]);
            }
        }
    }
}

// ---------------- GATv2: warp per dst node, online softmax over CSR edges ---
// lane l owns flat indices [8l, 8l+8) of [H=4, C=64]; head = l>>3
__device__ __forceinline__ void unpack8(uint4 q, float* f) {
    __nv_bfloat162 h0 = *(__nv_bfloat162*)&q.x;
    __nv_bfloat162 h1 = *(__nv_bfloat162*)&q.y;
    __nv_bfloat162 h2 = *(__nv_bfloat162*)&q.z;
    __nv_bfloat162 h3 = *(__nv_bfloat162*)&q.w;
    f[0] = __bfloat162float(h0.x); f[1] = __bfloat162float(h0.y);
    f[2] = __bfloat162float(h1.x); f[3] = __bfloat162float(h1.y);
    f[4] = __bfloat162float(h2.x); f[5] = __bfloat162float(h2.y);
    f[6] = __bfloat162float(h3.x); f[7] = __bfloat162float(h3.y);
}

__global__ void k_gat(const float* __restrict__ att, const float* __restrict__ bias, int N) {
    int warp = (blockIdx.x * blockDim.x + threadIdx.x) >> 5;
    int lane = threadIdx.x & 31;
    if (warp >= N) return;
    const uint4* xlh = (const uint4*)g_xlh;   // row = 32 uint4
    const float4* xr4 = (const float4*)g_xr;

    float4 r0 = xr4[(size_t)warp * 64 + lane * 2];
    float4 r1 = xr4[(size_t)warp * 64 + lane * 2 + 1];
    float rr[8] = {r0.x, r0.y, r0.z, r0.w, r1.x, r1.y, r1.z, r1.w};
    float4 a0 = ((const float4*)att)[lane * 2];
    float4 a1 = ((const float4*)att)[lane * 2 + 1];
    float at[8] = {a0.x, a0.y, a0.z, a0.w, a1.x, a1.y, a1.z, a1.w};

    float m = -1e30f, s = 0.f;
    float acc[8] = {0.f, 0.f, 0.f, 0.f, 0.f, 0.f, 0.f, 0.f};
    int e0 = g_rowptr[warp], e1 = g_rowptr[warp + 1];
    int e = e0;
    for (; e + 2 <= e1; e += 2) {             // 2-edge unroll
        int j0 = g_ssrc[e], j1 = g_ssrc[e + 1];
        uint4 q0 = xlh[(size_t)j0 * 32 + lane];
        uint4 q1 = xlh[(size_t)j1 * 32 + lane];
        float f0[8], f1[8];
        unpack8(q0, f0);
        unpack8(q1, f1);
        float p0 = 0.f, p1 = 0.f;
#pragma unroll
        for (int k = 0; k < 8; k++) {
            float t0 = f0[k] + rr[k];
            float t1 = f1[k] + rr[k];
            t0 = (t0 > 0.f) ? t0 : 0.2f * t0;
            t1 = (t1 > 0.f) ? t1 : 0.2f * t1;
            p0 += at[k] * t0;
            p1 += at[k] * t1;
        }
        p0 += __shfl_xor_sync(0xffffffffu, p0, 1);
        p1 += __shfl_xor_sync(0xffffffffu, p1, 1);
        p0 += __shfl_xor_sync(0xffffffffu, p0, 2);
        p1 += __shfl_xor_sync(0xffffffffu, p1, 2);
        p0 += __shfl_xor_sync(0xffffffffu, p0, 4);
        p1 += __shfl_xor_sync(0xffffffffu, p1, 4);
        float mn = fmaxf(m, fmaxf(p0, p1));
        float sc = __expf(m - mn);
        float w0 = __expf(p0 - mn);
        float w1 = __expf(p1 - mn);
        s = s * sc + w0 + w1;
#pragma unroll
        for (int k = 0; k < 8; k++)
            acc[k] = acc[k] * sc + w0 * f0[k] + w1 * f1[k];
        m = mn;
    }
    if (e < e1) {                             // tail (0 or 1 edge)
        int j = g_ssrc[e];
        uint4 q = xlh[(size_t)j * 32 + lane];
        float f[8];
        unpack8(q, f);
        float p = 0.f;
#pragma unroll
        for (int k = 0; k < 8; k++) {
            float t = f[k] + rr[k];
            t = (t > 0.f) ? t : 0.2f * t;
            p += at[k] * t;
        }
        p += __shfl_xor_sync(0xffffffffu, p, 1);
        p += __shfl_xor_sync(0xffffffffu, p, 2);
        p += __shfl_xor_sync(0xffffffffu, p, 4);
        float mn = fmaxf(m, p);
        float sc = __expf(m - mn);
        float w  = __expf(p - mn);
        s = s * sc + w;
#pragma unroll
        for (int k = 0; k < 8; k++) acc[k] = acc[k] * sc + w * f[k];
        m = mn;
    }
    float inv = 1.0f / s;
#pragma unroll
    for (int k = 0; k < 8; k++) {
        float v = acc[k] * inv;                    // per-head normalized
        v += __shfl_xor_sync(0xffffffffu, v, 8);   // sum over 4 heads
        v += __shfl_xor_sync(0xffffffffu, v, 16);
        acc[k] = v;
    }
    if (lane < 8) {
        float4 b0 = ((const float4*)bias)[lane * 2];
        float4 b1 = ((const float4*)bias)[lane * 2 + 1];
        float bv[8] = {b0.x, b0.y, b0.z, b0.w, b1.x, b1.y, b1.z, b1.w};
        float o[8];
#pragma unroll
        for (int k = 0; k < 8; k++) o[k] = 0.25f * acc[k] + bv[k];
        float4 w0 = make_float4(o[0], o[1], o[2], o[3]);
        float4 w1 = make_float4(o[4], o[5], o[6], o[7]);
        ((float4*)g_gat)[(size_t)warp * 16 + lane * 2]     = w0;
        ((float4*)g_gat)[(size_t)warp * 16 + lane * 2 + 1] = w1;
    }
}

// ---------------- BatchNorm (training stats) + GELU + residual --------------
__global__ void k_bnstats(int N) {
    int c = threadIdx.x & 63;
    int rg = threadIdx.x >> 6;                  // 0..3
    float s = 0.f, q = 0.f;
    for (int r = blockIdx.x * 4 + rg; r < N; r += gridDim.x * 4) {
        float v = g_gat[(size_t)r * 64 + c];
        s += v; q += v * v;
    }
    __shared__ float ss[4][64], qq[4][64];
    ss[rg][c] = s; qq[rg][c] = q;
    __syncthreads();
    if (rg == 0) {
        s = ss[0][c] + ss[1][c] + ss[2][c] + ss[3][c];
        q = qq[0][c] + qq[1][c] + qq[2][c] + qq[3][c];
        g_psum[blockIdx.x * 64 + c] = s;
        g_psq [blockIdx.x * 64 + c] = q;
    }
}

__global__ void k_bnfin(const float* __restrict__ gamma, const float* __restrict__ beta,
                        int N, int nblk) {
    int c = threadIdx.x;
    float s = 0.f, q = 0.f;
    for (int b = 0; b < nblk; b++) { s += g_psum[b * 64 + c]; q += g_psq[b * 64 + c]; }
    float mu = s / (float)N;
    float var = q / (float)N - mu * mu;
    float iv = rsqrtf(var + 1e-5f);
    float a = gamma[c] * iv;
    g_bna[c] = a;
    g_bnb[c] = beta[c] - a * mu;
}

__global__ void k_bngelu(int total, int residual) {
    int i = blockIdx.x * blockDim.x + threadIdx.x;
    if (i >= total) return;
    int c = i & 63;
    float t = g_bna[c] * g_gat[i] + g_bnb[c];
    float ge = 0.5f * t * (1.0f + erff(t * 0.70710678118654752f));
    g_h[i] = residual ? (ge + g_h[i]) : ge;
}

// ---------------- pooling + heads -------------------------------------------
__global__ void k_bounds(const int* __restrict__ batch, int N, int G) {
    int i = blockIdx.x * blockDim.x + threadIdx.x;
    if (i >= N) return;
    int b = batch[i];
    int prev = (i == 0) ? -1 : batch[i - 1];
    for (int g = prev + 1; g <= b; g++) g_gstart[g] = i;
    if (i == N - 1) for (int g = b + 1; g <= G; g++) g_gstart[g] = N;
}

__global__ void k_pool(int G) {
    int g = blockIdx.x, c = threadIdx.x;   // 64 threads
    float s = 0.f;
    int e = g_gstart[g + 1];
    for (int n = g_gstart[g]; n < e; n++) s += g_h[(size_t)n * 64 + c];
    g_pool[(size_t)g * 64 + c] = s;
}

__global__ void k_heads(const float* __restrict__ Wmu, const float* __restrict__ bmu,
                        const float* __restrict__ Wlv, const float* __restrict__ blv,
                        float* __restrict__ out, int G) {
    int g = blockIdx.x, t = threadIdx.x;   // 128 threads
    __shared__ float p[64];
    if (t < 64) p[t] = g_pool[(size_t)g * 64 + t];
    __syncthreads();
    int c = t & 63;
    const float* W = (t < 64) ? Wmu : Wlv;
    float s = (t < 64) ? bmu[c] : blv[c];
    for (int k = 0; k < 64; k++) s += p[k] * W[k * 64 + c];
    out[((t < 64) ? 0 : (size_t)G * 64) + (size_t)g * 64 + c] = s;
}

// ---------------- host orchestration ----------------------------------------
extern "C" void kernel_launch(void* const* d_in, const int* in_sizes, int n_in,
                              void* d_out, int out_size) {
    // metadata: x, edge_src, edge_dst, batch, [num_graphs],
    //           (Wl,Wr,att,b,g,be) x3, Wmu, bmu, Wlv, blv
    bool has_ng = (n_in >= 27);
    auto IX = [&](int i) { return has_ng ? i : (i > 4 ? i - 1 : i); };

    const float* x     = (const float*)d_in[0];
    const int*   esrc  = (const int*)d_in[1];
    const int*   edst  = (const int*)d_in[2];
    const int*   batch = (const int*)d_in[3];

    int N  = in_sizes[0] / 64;
    int E  = in_sizes[1];
    int EA = E + N;
    int G  = out_size / 128;   // 2 * G * 64

    void* hptr_v = nullptr;
    cudaGetSymbolAddress(&hptr_v, g_h);
    const float* hbuf = (const float*)hptr_v;

    // ---- deterministic CSR: bucket scatter + per-bucket index sort ----
    // (g_deg statically zero at load; k_place re-zeroes it each execution)
    k_deg        <<<(EA + 255) / 256, 256>>>(edst, E, EA);
    k_scan       <<<1, 1024>>>(N, EA);
    k_place      <<<(EA + 255) / 256, 256>>>(edst, E, EA, N);
    k_sortbuckets<<<(N + 127) / 128, 128>>>(esrc, E, N);

    // ---- 3 GATv2 layers ----
    const float* hin = x;
    for (int L = 0; L < 3; L++) {
        int b0 = 5 + 6 * L;
        const float* Wl  = (const float*)d_in[IX(b0 + 0)];
        const float* Wr  = (const float*)d_in[IX(b0 + 1)];
        const float* att = (const float*)d_in[IX(b0 + 2)];
        const float* bb  = (const float*)d_in[IX(b0 + 3)];
        const float* gg  = (const float*)d_in[IX(b0 + 4)];
        const float* be  = (const float*)d_in[IX(b0 + 5)];

        dim3 gg_gemm((N + 127) / 128, 8);
        k_gemm   <<<gg_gemm, 256>>>(hin, Wl, Wr, N);
        k_gat    <<<(N * 32 + 255) / 256, 256>>>(att, bb, N);
        k_bnstats<<<256, 256>>>(N);
        k_bnfin  <<<1, 64>>>(gg, be, N, 256);
        k_bngelu <<<(N * 64 + 255) / 256, 256>>>(N * 64, (L > 0) ? 1 : 0);
        hin = hbuf;
    }

    // ---- pool + heads ----
    const float* Wmu = (const float*)d_in[IX(23)];
    const float* bmu = (const float*)d_in[IX(24)];
    const float* Wlv = (const float*)d_in[IX(25)];
    const float* blv = (const float*)d_in[IX(26)];

    k_bounds<<<(N + 255) / 256, 256>>>(batch, N, G);
    k_pool  <<<G, 64>>>(G);
    k_heads <<<G, 128>>>(Wmu, bmu, Wlv, blv, (float*)d_out, G);
}

// round 14
// speedup vs baseline: 1.5213x; 1.0567x over previous
#include <cuda_runtime.h>
#include <cuda_bf16.h>
#include <math.h>
#include <stdint.h>

// ---------------- static scratch (device globals; no allocation allowed) -----
#define MAXN   50048
#define MAXE   800000
#define MAXEA  (MAXE + MAXN)
#define HD     256        // H*HID
#define FD     64
#define MAXG   1024
#define SCAP   96         // smem bucket-sort capacity per node
#define MAXBLK 6256       // ceil(MAXN/8) gat blocks

__device__ int   g_deg[MAXN];         // zero at load; re-zeroed by k_place each run
__device__ int   g_cursor[MAXN];
__device__ int   g_rowptr[MAXN + 1];
__device__ int   g_sidx[MAXEA];
__device__ int   g_ssrc[MAXEA];
__device__ __nv_bfloat162 g_xlh[(size_t)MAXN * (HD / 2)];   // xl in bf16
__device__ float g_xr[(size_t)MAXN * HD];
__device__ float g_gat[(size_t)MAXN * FD];
__device__ float g_h[(size_t)MAXN * FD];
__device__ float g_ps2[(size_t)MAXBLK * FD];
__device__ float g_pq2[(size_t)MAXBLK * FD];
__device__ float g_bna[FD];
__device__ float g_bnb[FD];
__device__ int   g_gstart[MAXG + 1];
__device__ float g_pool[(size_t)MAXG * FD];

// ---------------- deterministic CSR build: bucket + per-bucket sort ---------
__global__ void k_deg(const int* __restrict__ edst, int E, int EA) {
    int i = blockIdx.x * blockDim.x + threadIdx.x;
    if (i >= EA) return;
    int d = (i < E) ? edst[i] : (i - E);       // self loops appended
    atomicAdd(&g_deg[d], 1);
}

__global__ void k_scan(int N, int EA) {
    __shared__ int sm[1024];
    int t = threadIdx.x;
    int chunk = (N + 1023) / 1024;
    int s = t * chunk, e = min(s + chunk, N);
    int sum = 0;
    for (int i = s; i < e; i++) sum += g_deg[i];
    sm[t] = sum;
    __syncthreads();
    for (int off = 1; off < 1024; off <<= 1) {
        int v = (t >= off) ? sm[t - off] : 0;
        __syncthreads();
        sm[t] += v;
        __syncthreads();
    }
    int base = sm[t] - sum;   // exclusive prefix
    for (int i = s; i < e; i++) {
        g_rowptr[i] = base;
        g_cursor[i] = base;
        base += g_deg[i];
    }
    if (t == 0) g_rowptr[N] = EA;
}

__global__ void k_place(const int* __restrict__ edst, int E, int EA, int N) {
    int i = blockIdx.x * blockDim.x + threadIdx.x;
    if (i < N) g_deg[i] = 0;     // g_deg dead after k_scan; reset for next run
    if (i >= EA) return;
    int d = (i < E) ? edst[i] : (i - E);
    int pos = atomicAdd(&g_cursor[d], 1);
    g_sidx[pos] = i;             // store original edge index (unique key)
}

// thread per node: sort its bucket by original edge index -> deterministic
__global__ void k_sortbuckets(const int* __restrict__ esrc, int E, int N) {
    __shared__ int buf[SCAP * 128];
    int tid = threadIdx.x;                    // 128 threads
    int node = blockIdx.x * 128 + tid;
    if (node >= N) return;
    int e0 = g_rowptr[node], e1 = g_rowptr[node + 1];
    int deg = e1 - e0;
    if (deg <= SCAP) {
        for (int j = 0; j < deg; j++) buf[j * 128 + tid] = g_sidx[e0 + j];
        for (int a = 1; a < deg; a++) {
            int v = buf[a * 128 + tid];
            int j = a - 1;
            while (j >= 0 && buf[j * 128 + tid] > v) {
                buf[(j + 1) * 128 + tid] = buf[j * 128 + tid];
                j--;
            }
            buf[(j + 1) * 128 + tid] = v;
        }
        for (int j = 0; j < deg; j++) {
            int v = buf[j * 128 + tid];
            g_ssrc[e0 + j] = (v < E) ? esrc[v] : (v - E);
        }
    } else {
        int* b = g_sidx + e0;                 // rare fallback: global in-place
        for (int a = 1; a < deg; a++) {
            int v = b[a];
            int j = a - 1;
            while (j >= 0 && b[j] > v) { b[j + 1] = b[j]; j--; }
            b[j + 1] = v;
        }
        for (int j = 0; j < deg; j++) {
            int v = b[j];
            g_ssrc[e0 + j] = (v < E) ? esrc[v] : (v - E);
        }
    }
}

// ---------------- TF32 tensor-core GEMM: C[N,256] = A[N,64] @ W[64,256] -----
// xl half of the output is stored as bf16 (for the GAT gather); xr half fp32.
__device__ __forceinline__ uint32_t f2tf(float f) {
    uint32_t u;
    asm("cvt.rna.tf32.f32 %0, %1;" : "=r"(u) : "f"(f));
    return u;
}
__device__ __forceinline__ void mma_tf32(float* c, const uint32_t* a, const uint32_t* b) {
    asm volatile("mma.sync.aligned.m16n8k8.row.col.f32.tf32.tf32.f32 "
                 "{%0,%1,%2,%3}, {%4,%5,%6,%7}, {%8,%9}, {%0,%1,%2,%3};"
                 : "+f"(c[0]), "+f"(c[1]), "+f"(c[2]), "+f"(c[3])
                 : "r"(a[0]), "r"(a[1]), "r"(a[2]), "r"(a[3]),
                   "r"(b[0]), "r"(b[1]));
}
// XOR swizzles (conflict-free fragment loads, 16B-aligned fills preserved)
#define ASW(r, c) ((c) ^ (((r) & 7) << 2))
#define BSW(k, n) ((n) ^ (((k) & 3) << 3))

// tile 128 rows x 64 cols, 256 threads (8 warps = 4x2 of 32x32 warptiles)
__global__ void k_gemm(const float* __restrict__ A, const float* __restrict__ Wl,
                       const float* __restrict__ Wr, int N) {
    __shared__ uint32_t As[128][64];   // 32KB, tf32
    __shared__ uint32_t Bs[64][64];    // 16KB, tf32
    int tid = threadIdx.x;
    int wid = tid >> 5, lane = tid & 31;
    int m0 = blockIdx.x * 128;
    int cb = blockIdx.y * 64;
    bool is_xl = (cb < 256);
    const float* W = is_xl ? Wl : Wr;
    int c0 = is_xl ? cb : cb - 256;

    const float4* A4 = (const float4*)A;
#pragma unroll
    for (int q = 0; q < 8; q++) {             // 2048 float4
        int fi = q * 256 + tid;
        int r = fi >> 4, c4 = fi & 15;
        float4 v = make_float4(0.f, 0.f, 0.f, 0.f);
        if (m0 + r < N) v = A4[(size_t)(m0 + r) * 16 + c4];
        uint4 u = make_uint4(f2tf(v.x), f2tf(v.y), f2tf(v.z), f2tf(v.w));
        *(uint4*)&As[r][ASW(r, c4 * 4)] = u;
    }
    const float4* W4 = (const float4*)W;      // W is [64,256]: 64 float4/row
#pragma unroll
    for (int q = 0; q < 4; q++) {             // 1024 float4
        int fi = q * 256 + tid;
        int k = fi >> 4, n4 = fi & 15;
        float4 v = W4[(size_t)k * 64 + (c0 >> 2) + n4];
        uint4 u = make_uint4(f2tf(v.x), f2tf(v.y), f2tf(v.z), f2tf(v.w));
        *(uint4*)&Bs[k][BSW(k, n4 * 4)] = u;
    }
    __syncthreads();

    int wm = (wid & 3) * 32, wn = (wid >> 2) * 32;
    int ar = lane >> 2, ac = lane & 3;
    float acc[2][4][4];
#pragma unroll
    for (int mi = 0; mi < 2; mi++)
#pragma unroll
        for (int ni = 0; ni < 4; ni++)
#pragma unroll
            for (int c = 0; c < 4; c++) acc[mi][ni][c] = 0.f;

#pragma unroll
    for (int ks = 0; ks < 8; ks++) {
        uint32_t a[2][4], b[4][2];
#pragma unroll
        for (int mi = 0; mi < 2; mi++) {
            int r0 = wm + mi * 16 + ar, r1 = r0 + 8;
            int cA = ks * 8 + ac;
            a[mi][0] = As[r0][ASW(r0, cA)];
            a[mi][1] = As[r1][ASW(r1, cA)];
            a[mi][2] = As[r0][ASW(r0, cA + 4)];
            a[mi][3] = As[r1][ASW(r1, cA + 4)];
        }
#pragma unroll
        for (int ni = 0; ni < 4; ni++) {
            int nn = wn + ni * 8 + ar;
            int k0 = ks * 8 + ac, k1 = k0 + 4;
            b[ni][0] = Bs[k0][BSW(k0, nn)];
            b[ni][1] = Bs[k1][BSW(k1, nn)];
        }
#pragma unroll
        for (int mi = 0; mi < 2; mi++)
#pragma unroll
            for (int ni = 0; ni < 4; ni++)
                mma_tf32(acc[mi][ni], a[mi], b[ni]);
    }
    // epilogue: rows < MAXN always (391*128 = 50048 = MAXN), no guard needed
    if (is_xl) {
#pragma unroll
        for (int mi = 0; mi < 2; mi++) {
            int r = m0 + wm + mi * 16 + ar;
#pragma unroll
            for (int ni = 0; ni < 4; ni++) {
                int c = c0 + wn + ni * 8 + ac * 2;   // even col; pair (c, c+1)
                g_xlh[(size_t)r * 128 + (c >> 1)] =
                    __floats2bfloat162_rn(acc[mi][ni][0], acc[mi][ni][1]);
                g_xlh[(size_t)(r + 8) * 128 + (c >> 1)] =
                    __floats2bfloat162_rn(acc[mi][ni][2], acc[mi][ni][3]);
            }
        }
    } else {
#pragma unroll
        for (int mi = 0; mi < 2; mi++) {
            int r = m0 + wm + mi * 16 + ar;
#pragma unroll
            for (int ni = 0; ni < 4; ni++) {
                int c = c0 + wn + ni * 8 + ac * 2;
                *(float2*)&g_xr[(size_t)r * 256 + c] =
                    make_float2(acc[mi][ni][0], acc[mi][ni][1]);
                *(float2*)&g_xr[(size_t)(r + 8) * 256 + c] =
                    make_float2(acc[mi][ni][2], acc[mi][ni][3]);
            }
        }
    }
}

// ---------------- GATv2: warp per dst node + fused BN partial stats ---------
// lane l owns flat indices [8l, 8l+8) of [H=4, C=64]; head = l>>3
__device__ __forceinline__ void unpack8(uint4 q, float* f) {
    __nv_bfloat162 h0 = *(__nv_bfloat162*)&q.x;
    __nv_bfloat162 h1 = *(__nv_bfloat162*)&q.y;
    __nv_bfloat162 h2 = *(__nv_bfloat162*)&q.z;
    __nv_bfloat162 h3 = *(__nv_bfloat162*)&q.w;
    f[0] = __bfloat162float(h0.x); f[1] = __bfloat162float(h0.y);
    f[2] = __bfloat162float(h1.x); f[3] = __bfloat162float(h1.y);
    f[4] = __bfloat162float(h2.x); f[5] = __bfloat162float(h2.y);
    f[6] = __bfloat162float(h3.x); f[7] = __bfloat162float(h3.y);
}

__global__ void k_gat(const float* __restrict__ att, const float* __restrict__ bias, int N) {
    __shared__ float ssum[8][64];
    __shared__ float ssq[8][64];
    int w = threadIdx.x >> 5;
    int lane = threadIdx.x & 31;
    int node = blockIdx.x * 8 + w;
    bool valid = node < N;
    int nidx = valid ? node : 0;
    const uint4* xlh = (const uint4*)g_xlh;   // row = 32 uint4
    const float4* xr4 = (const float4*)g_xr;

    float4 r0 = xr4[(size_t)nidx * 64 + lane * 2];
    float4 r1 = xr4[(size_t)nidx * 64 + lane * 2 + 1];
    float rr[8] = {r0.x, r0.y, r0.z, r0.w, r1.x, r1.y, r1.z, r1.w};
    float4 a0 = ((const float4*)att)[lane * 2];
    float4 a1 = ((const float4*)att)[lane * 2 + 1];
    float at[8] = {a0.x, a0.y, a0.z, a0.w, a1.x, a1.y, a1.z, a1.w};

    float m = -1e30f, s = 0.f;
    float acc[8] = {0.f, 0.f, 0.f, 0.f, 0.f, 0.f, 0.f, 0.f};
    int e0 = valid ? g_rowptr[node] : 0;
    int e1 = valid ? g_rowptr[node + 1] : 0;
    int e = e0;
    for (; e + 2 <= e1; e += 2) {             // 2-edge unroll
        int j0 = g_ssrc[e], j1 = g_ssrc[e + 1];
        uint4 q0 = xlh[(size_t)j0 * 32 + lane];
        uint4 q1 = xlh[(size_t)j1 * 32 + lane];
        float f0[8], f1[8];
        unpack8(q0, f0);
        unpack8(q1, f1);
        float p0 = 0.f, p1 = 0.f;
#pragma unroll
        for (int k = 0; k < 8; k++) {
            float t0 = f0[k] + rr[k];
            float t1 = f1[k] + rr[k];
            t0 = (t0 > 0.f) ? t0 : 0.2f * t0;
            t1 = (t1 > 0.f) ? t1 : 0.2f * t1;
            p0 += at[k] * t0;
            p1 += at[k] * t1;
        }
        p0 += __shfl_xor_sync(0xffffffffu, p0, 1);
        p1 += __shfl_xor_sync(0xffffffffu, p1, 1);
        p0 += __shfl_xor_sync(0xffffffffu, p0, 2);
        p1 += __shfl_xor_sync(0xffffffffu, p1, 2);
        p0 += __shfl_xor_sync(0xffffffffu, p0, 4);
        p1 += __shfl_xor_sync(0xffffffffu, p1, 4);
        float mn = fmaxf(m, fmaxf(p0, p1));
        float sc = __expf(m - mn);
        float w0 = __expf(p0 - mn);
        float w1 = __expf(p1 - mn);
        s = s * sc + w0 + w1;
#pragma unroll
        for (int k = 0; k < 8; k++)
            acc[k] = acc[k] * sc + w0 * f0[k] + w1 * f1[k];
        m = mn;
    }
    if (e < e1) {                             // tail (0 or 1 edge)
        int j = g_ssrc[e];
        uint4 q = xlh[(size_t)j * 32 + lane];
        float f[8];
        unpack8(q, f);
        float p = 0.f;
#pragma unroll
        for (int k = 0; k < 8; k++) {
            float t = f[k] + rr[k];
            t = (t > 0.f) ? t : 0.2f * t;
            p += at[k] * t;
        }
        p += __shfl_xor_sync(0xffffffffu, p, 1);
        p += __shfl_xor_sync(0xffffffffu, p, 2);
        p += __shfl_xor_sync(0xffffffffu, p, 4);
        float mn = fmaxf(m, p);
        float sc = __expf(m - mn);
        float ww = __expf(p - mn);
        s = s * sc + ww;
#pragma unroll
        for (int k = 0; k < 8; k++) acc[k] = acc[k] * sc + ww * f[k];
        m = mn;
    }
    float inv = 1.0f / s;
#pragma unroll
    for (int k = 0; k < 8; k++) {
        float v = acc[k] * inv;                    // per-head normalized
        v += __shfl_xor_sync(0xffffffffu, v, 8);   // sum over 4 heads
        v += __shfl_xor_sync(0xffffffffu, v, 16);
        acc[k] = v;
    }
    if (lane < 8) {
        float4 b0 = ((const float4*)bias)[lane * 2];
        float4 b1 = ((const float4*)bias)[lane * 2 + 1];
        float bv[8] = {b0.x, b0.y, b0.z, b0.w, b1.x, b1.y, b1.z, b1.w};
        float o[8];
#pragma unroll
        for (int k = 0; k < 8; k++) {
            o[k] = valid ? (0.25f * acc[k] + bv[k]) : 0.f;
            ssum[w][lane * 8 + k] = o[k];
            ssq[w][lane * 8 + k] = o[k] * o[k];
        }
        if (valid) {
            float4 w0 = make_float4(o[0], o[1], o[2], o[3]);
            float4 w1 = make_float4(o[4], o[5], o[6], o[7]);
            ((float4*)g_gat)[(size_t)node * 16 + lane * 2]     = w0;
            ((float4*)g_gat)[(size_t)node * 16 + lane * 2 + 1] = w1;
        }
    }
    __syncthreads();
    if (threadIdx.x < 64) {                   // per-block BN partials (fixed order)
        float s2 = 0.f, q2 = 0.f;
#pragma unroll
        for (int ww = 0; ww < 8; ww++) {
            s2 += ssum[ww][threadIdx.x];
            q2 += ssq[ww][threadIdx.x];
        }
        g_ps2[(size_t)blockIdx.x * 64 + threadIdx.x] = s2;
        g_pq2[(size_t)blockIdx.x * 64 + threadIdx.x] = q2;
    }
}

// ---------------- BN finalize: one block per channel, deterministic ---------
__global__ void k_bnfin2(const float* __restrict__ gamma, const float* __restrict__ beta,
                         int N, int nblk) {
    __shared__ float S[256], Q[256];
    int c = blockIdx.x;                       // 64 blocks
    int t = threadIdx.x;                      // 256 threads
    float s = 0.f, q = 0.f;
    for (int b = t; b < nblk; b += 256) {     // fixed per-thread stride order
        s += g_ps2[(size_t)b * 64 + c];
        q += g_pq2[(size_t)b * 64 + c];
    }
    S[t] = s; Q[t] = q;
    __syncthreads();
    for (int off = 128; off > 0; off >>= 1) { // fixed tree order
        if (t < off) { S[t] += S[t + off]; Q[t] += Q[t + off]; }
        __syncthreads();
    }
    if (t == 0) {
        float mu = S[0] / (float)N;
        float var = Q[0] / (float)N - mu * mu;
        float iv = rsqrtf(var + 1e-5f);
        float a = gamma[c] * iv;
        g_bna[c] = a;
        g_bnb[c] = beta[c] - a * mu;
    }
}

__global__ void k_bngelu(int total, int residual) {
    int i = blockIdx.x * blockDim.x + threadIdx.x;
    if (i >= total) return;
    int c = i & 63;
    float t = g_bna[c] * g_gat[i] + g_bnb[c];
    float ge = 0.5f * t * (1.0f + erff(t * 0.70710678118654752f));
    g_h[i] = residual ? (ge + g_h[i]) : ge;
}

// ---------------- pooling + heads -------------------------------------------
__global__ void k_bounds(const int* __restrict__ batch, int N, int G) {
    int i = blockIdx.x * blockDim.x + threadIdx.x;
    if (i >= N) return;
    int b = batch[i];
    int prev = (i == 0) ? -1 : batch[i - 1];
    for (int g = prev + 1; g <= b; g++) g_gstart[g] = i;
    if (i == N - 1) for (int g = b + 1; g <= G; g++) g_gstart[g] = N;
}

__global__ void k_pool(int G) {
    int g = blockIdx.x, c = threadIdx.x;   // 64 threads
    float s = 0.f;
    int e = g_gstart[g + 1];
    for (int n = g_gstart[g]; n < e; n++) s += g_h[(size_t)n * 64 + c];
    g_pool[(size_t)g * 64 + c] = s;
}

__global__ void k_heads(const float* __restrict__ Wmu, const float* __restrict__ bmu,
                        const float* __restrict__ Wlv, const float* __restrict__ blv,
                        float* __restrict__ out, int G) {
    int g = blockIdx.x, t = threadIdx.x;   // 128 threads
    __shared__ float p[64];
    if (t < 64) p[t] = g_pool[(size_t)g * 64 + t];
    __syncthreads();
    int c = t & 63;
    const float* W = (t < 64) ? Wmu : Wlv;
    float s = (t < 64) ? bmu[c] : blv[c];
    for (int k = 0; k < 64; k++) s += p[k] * W[k * 64 + c];
    out[((t < 64) ? 0 : (size_t)G * 64) + (size_t)g * 64 + c] = s;
}

// ---------------- host orchestration ----------------------------------------
extern "C" void kernel_launch(void* const* d_in, const int* in_sizes, int n_in,
                              void* d_out, int out_size) {
    // metadata: x, edge_src, edge_dst, batch, [num_graphs],
    //           (Wl,Wr,att,b,g,be) x3, Wmu, bmu, Wlv, blv
    bool has_ng = (n_in >= 27);
    auto IX = [&](int i) { return has_ng ? i : (i > 4 ? i - 1 : i); };

    const float* x     = (const float*)d_in[0];
    const int*   esrc  = (const int*)d_in[1];
    const int*   edst  = (const int*)d_in[2];
    const int*   batch = (const int*)d_in[3];

    int N  = in_sizes[0] / 64;
    int E  = in_sizes[1];
    int EA = E + N;
    int G  = out_size / 128;   // 2 * G * 64

    void* hptr_v = nullptr;
    cudaGetSymbolAddress(&hptr_v, g_h);
    const float* hbuf = (const float*)hptr_v;

    // ---- deterministic CSR: bucket scatter + per-bucket index sort ----
    // (g_deg statically zero at load; k_place re-zeroes it each execution)
    k_deg        <<<(EA + 255) / 256, 256>>>(edst, E, EA);
    k_scan       <<<1, 1024>>>(N, EA);
    k_place      <<<(EA + 255) / 256, 256>>>(edst, E, EA, N);
    k_sortbuckets<<<(N + 127) / 128, 128>>>(esrc, E, N);

    // ---- 3 GATv2 layers ----
    int gatblk = (N + 7) / 8;
    const float* hin = x;
    for (int L = 0; L < 3; L++) {
        int b0 = 5 + 6 * L;
        const float* Wl  = (const float*)d_in[IX(b0 + 0)];
        const float* Wr  = (const float*)d_in[IX(b0 + 1)];
        const float* att = (const float*)d_in[IX(b0 + 2)];
        const float* bb  = (const float*)d_in[IX(b0 + 3)];
        const float* gg  = (const float*)d_in[IX(b0 + 4)];
        const float* be  = (const float*)d_in[IX(b0 + 5)];

        dim3 gg_gemm((N + 127) / 128, 8);
        k_gemm  <<<gg_gemm, 256>>>(hin, Wl, Wr, N);
        k_gat   <<<gatblk, 256>>>(att, bb, N);
        k_bnfin2<<<64, 256>>>(gg, be, N, gatblk);
        k_bngelu<<<(N * 64 + 255) / 256, 256>>>(N * 64, (L > 0) ? 1 : 0);
        hin = hbuf;
    }

    // ---- pool + heads ----
    const float* Wmu = (const float*)d_in[IX(23)];
    const float* bmu = (const float*)d_in[IX(24)];
    const float* Wlv = (const float*)d_in[IX(25)];
    const float* blv = (const float*)d_in[IX(26)];

    k_bounds<<<(N + 255) / 256, 256>>>(batch, N, G);
    k_pool  <<<G, 64>>>(G);
    k_heads <<<G, 128>>>(Wmu, bmu, Wlv, blv, (float*)d_out, G);
}

// round 15
// speedup vs baseline: 1.5217x; 1.0003x over previous
#include <cuda_runtime.h>
#include <cuda_bf16.h>
#include <math.h>
#include <stdint.h>

// ---------------- static scratch (device globals; no allocation allowed) -----
#define MAXN   50048
#define MAXE   800000
#define MAXEA  (MAXE + MAXN)
#define HD     256        // H*HID
#define FD     64
#define MAXG   1024
#define SCAP   96         // smem bucket-sort capacity per node
#define MAXBLK 6256       // ceil(MAXN/8) gat blocks

__device__ int   g_deg[MAXN];         // zero at load; re-zeroed by k_place each run
__device__ int   g_cursor[MAXN];
__device__ int   g_rowptr[MAXN + 1];
__device__ int   g_sidx[MAXEA];
__device__ int   g_ssrc[MAXEA];
__device__ __nv_bfloat162 g_xlh[(size_t)MAXN * (HD / 2)];   // xl in bf16
__device__ float g_xr[(size_t)MAXN * HD];
__device__ float g_gat[(size_t)MAXN * FD];
__device__ float g_h[(size_t)MAXN * FD];
__device__ float g_ps2[(size_t)MAXBLK * FD];
__device__ float g_pq2[(size_t)MAXBLK * FD];
__device__ float g_bna[FD];
__device__ float g_bnb[FD];
__device__ int   g_gstart[MAXG + 1];
__device__ float g_pool[(size_t)MAXG * FD];

// ---------------- deterministic CSR build: bucket + per-bucket sort ---------
__global__ void k_deg(const int* __restrict__ edst, int E, int EA) {
    int i = blockIdx.x * blockDim.x + threadIdx.x;
    if (i >= EA) return;
    int d = (i < E) ? edst[i] : (i - E);       // self loops appended
    atomicAdd(&g_deg[d], 1);
}

__global__ void k_scan(int N, int EA) {
    __shared__ int sm[1024];
    int t = threadIdx.x;
    int chunk = (N + 1023) / 1024;
    int s = t * chunk, e = min(s + chunk, N);
    int sum = 0;
    for (int i = s; i < e; i++) sum += g_deg[i];
    sm[t] = sum;
    __syncthreads();
    for (int off = 1; off < 1024; off <<= 1) {
        int v = (t >= off) ? sm[t - off] : 0;
        __syncthreads();
        sm[t] += v;
        __syncthreads();
    }
    int base = sm[t] - sum;   // exclusive prefix
    for (int i = s; i < e; i++) {
        g_rowptr[i] = base;
        g_cursor[i] = base;
        base += g_deg[i];
    }
    if (t == 0) g_rowptr[N] = EA;
}

__global__ void k_place(const int* __restrict__ edst, int E, int EA, int N) {
    int i = blockIdx.x * blockDim.x + threadIdx.x;
    if (i < N) g_deg[i] = 0;     // g_deg dead after k_scan; reset for next run
    if (i >= EA) return;
    int d = (i < E) ? edst[i] : (i - E);
    int pos = atomicAdd(&g_cursor[d], 1);
    g_sidx[pos] = i;             // store original edge index (unique key)
}

// thread per node: sort its bucket by original edge index -> deterministic
__global__ void k_sortbuckets(const int* __restrict__ esrc, int E, int N) {
    __shared__ int buf[SCAP * 128];
    int tid = threadIdx.x;                    // 128 threads
    int node = blockIdx.x * 128 + tid;
    if (node >= N) return;
    int e0 = g_rowptr[node], e1 = g_rowptr[node + 1];
    int deg = e1 - e0;
    if (deg <= SCAP) {
        for (int j = 0; j < deg; j++) buf[j * 128 + tid] = g_sidx[e0 + j];
        for (int a = 1; a < deg; a++) {
            int v = buf[a * 128 + tid];
            int j = a - 1;
            while (j >= 0 && buf[j * 128 + tid] > v) {
                buf[(j + 1) * 128 + tid] = buf[j * 128 + tid];
                j--;
            }
            buf[(j + 1) * 128 + tid] = v;
        }
        for (int j = 0; j < deg; j++) {
            int v = buf[j * 128 + tid];
            g_ssrc[e0 + j] = (v < E) ? esrc[v] : (v - E);
        }
    } else {
        int* b = g_sidx + e0;                 // rare fallback: global in-place
        for (int a = 1; a < deg; a++) {
            int v = b[a];
            int j = a - 1;
            while (j >= 0 && b[j] > v) { b[j + 1] = b[j]; j--; }
            b[j + 1] = v;
        }
        for (int j = 0; j < deg; j++) {
            int v = b[j];
            g_ssrc[e0 + j] = (v < E) ? esrc[v] : (v - E);
        }
    }
}

// ---------------- TF32 tensor-core GEMM: C[N,256] = A[N,64] @ W[64,256] -----
// xl half of the output is stored as bf16 (for the GAT gather); xr half fp32.
__device__ __forceinline__ uint32_t f2tf(float f) {
    uint32_t u;
    asm("cvt.rna.tf32.f32 %0, %1;" : "=r"(u) : "f"(f));
    return u;
}
__device__ __forceinline__ void mma_tf32(float* c, const uint32_t* a, const uint32_t* b) {
    asm volatile("mma.sync.aligned.m16n8k8.row.col.f32.tf32.tf32.f32 "
                 "{%0,%1,%2,%3}, {%4,%5,%6,%7}, {%8,%9}, {%0,%1,%2,%3};"
                 : "+f"(c[0]), "+f"(c[1]), "+f"(c[2]), "+f"(c[3])
                 : "r"(a[0]), "r"(a[1]), "r"(a[2]), "r"(a[3]),
                   "r"(b[0]), "r"(b[1]));
}
// XOR swizzles (conflict-free fragment loads, 16B-aligned fills preserved)
#define ASW(r, c) ((c) ^ (((r) & 7) << 2))
#define BSW(k, n) ((n) ^ (((k) & 3) << 3))

// tile 128 rows x 64 cols, 256 threads (8 warps = 4x2 of 32x32 warptiles)
__global__ void k_gemm(const float* __restrict__ A, const float* __restrict__ Wl,
                       const float* __restrict__ Wr, int N) {
    __shared__ uint32_t As[128][64];   // 32KB, tf32
    __shared__ uint32_t Bs[64][64];    // 16KB, tf32
    int tid = threadIdx.x;
    int wid = tid >> 5, lane = tid & 31;
    int m0 = blockIdx.x * 128;
    int cb = blockIdx.y * 64;
    bool is_xl = (cb < 256);
    const float* W = is_xl ? Wl : Wr;
    int c0 = is_xl ? cb : cb - 256;

    const float4* A4 = (const float4*)A;
#pragma unroll
    for (int q = 0; q < 8; q++) {             // 2048 float4
        int fi = q * 256 + tid;
        int r = fi >> 4, c4 = fi & 15;
        float4 v = make_float4(0.f, 0.f, 0.f, 0.f);
        if (m0 + r < N) v = A4[(size_t)(m0 + r) * 16 + c4];
        uint4 u = make_uint4(f2tf(v.x), f2tf(v.y), f2tf(v.z), f2tf(v.w));
        *(uint4*)&As[r][ASW(r, c4 * 4)] = u;
    }
    const float4* W4 = (const float4*)W;      // W is [64,256]: 64 float4/row
#pragma unroll
    for (int q = 0; q < 4; q++) {             // 1024 float4
        int fi = q * 256 + tid;
        int k = fi >> 4, n4 = fi & 15;
        float4 v = W4[(size_t)k * 64 + (c0 >> 2) + n4];
        uint4 u = make_uint4(f2tf(v.x), f2tf(v.y), f2tf(v.z), f2tf(v.w));
        *(uint4*)&Bs[k][BSW(k, n4 * 4)] = u;
    }
    __syncthreads();

    int wm = (wid & 3) * 32, wn = (wid >> 2) * 32;
    int ar = lane >> 2, ac = lane & 3;
    float acc[2][4][4];
#pragma unroll
    for (int mi = 0; mi < 2; mi++)
#pragma unroll
        for (int ni = 0; ni < 4; ni++)
#pragma unroll
            for (int c = 0; c < 4; c++) acc[mi][ni][c] = 0.f;

#pragma unroll
    for (int ks = 0; ks < 8; ks++) {
        uint32_t a[2][4], b[4][2];
#pragma unroll
        for (int mi = 0; mi < 2; mi++) {
            int r0 = wm + mi * 16 + ar, r1 = r0 + 8;
            int cA = ks * 8 + ac;
            a[mi][0] = As[r0][ASW(r0, cA)];
            a[mi][1] = As[r1][ASW(r1, cA)];
            a[mi][2] = As[r0][ASW(r0, cA + 4)];
            a[mi][3] = As[r1][ASW(r1, cA + 4)];
        }
#pragma unroll
        for (int ni = 0; ni < 4; ni++) {
            int nn = wn + ni * 8 + ar;
            int k0 = ks * 8 + ac, k1 = k0 + 4;
            b[ni][0] = Bs[k0][BSW(k0, nn)];
            b[ni][1] = Bs[k1][BSW(k1, nn)];
        }
#pragma unroll
        for (int mi = 0; mi < 2; mi++)
#pragma unroll
            for (int ni = 0; ni < 4; ni++)
                mma_tf32(acc[mi][ni], a[mi], b[ni]);
    }
    // epilogue: rows < MAXN always (391*128 = 50048 = MAXN), no guard needed
    if (is_xl) {
#pragma unroll
        for (int mi = 0; mi < 2; mi++) {
            int r = m0 + wm + mi * 16 + ar;
#pragma unroll
            for (int ni = 0; ni < 4; ni++) {
                int c = c0 + wn + ni * 8 + ac * 2;   // even col; pair (c, c+1)
                g_xlh[(size_t)r * 128 + (c >> 1)] =
                    __floats2bfloat162_rn(acc[mi][ni][0], acc[mi][ni][1]);
                g_xlh[(size_t)(r + 8) * 128 + (c >> 1)] =
                    __floats2bfloat162_rn(acc[mi][ni][2], acc[mi][ni][3]);
            }
        }
    } else {
#pragma unroll
        for (int mi = 0; mi < 2; mi++) {
            int r = m0 + wm + mi * 16 + ar;
#pragma unroll
            for (int ni = 0; ni < 4; ni++) {
                int c = c0 + wn + ni * 8 + ac * 2;
                *(float2*)&g_xr[(size_t)r * 256 + c] =
                    make_float2(acc[mi][ni][0], acc[mi][ni][1]);
                *(float2*)&g_xr[(size_t)(r + 8) * 256 + c] =
                    make_float2(acc[mi][ni][2], acc[mi][ni][3]);
            }
        }
    }
}

// ---------------- GATv2: warp per dst node + fused BN partial stats ---------
// lane l owns flat indices [8l, 8l+8) of [H=4, C=64]; head = l>>3
// __launch_bounds__(256,4): cap regs at 64 -> 4 blocks/SM (8 warps/SMSP)
__device__ __forceinline__ void unpack8(uint4 q, float* f) {
    __nv_bfloat162 h0 = *(__nv_bfloat162*)&q.x;
    __nv_bfloat162 h1 = *(__nv_bfloat162*)&q.y;
    __nv_bfloat162 h2 = *(__nv_bfloat162*)&q.z;
    __nv_bfloat162 h3 = *(__nv_bfloat162*)&q.w;
    f[0] = __bfloat162float(h0.x); f[1] = __bfloat162float(h0.y);
    f[2] = __bfloat162float(h1.x); f[3] = __bfloat162float(h1.y);
    f[4] = __bfloat162float(h2.x); f[5] = __bfloat162float(h2.y);
    f[6] = __bfloat162float(h3.x); f[7] = __bfloat162float(h3.y);
}

__global__ void __launch_bounds__(256, 4)
k_gat(const float* __restrict__ att, const float* __restrict__ bias, int N) {
    __shared__ float ssum[8][64];
    __shared__ float ssq[8][64];
    int w = threadIdx.x >> 5;
    int lane = threadIdx.x & 31;
    int node = blockIdx.x * 8 + w;
    bool valid = node < N;
    int nidx = valid ? node : 0;
    const uint4* xlh = (const uint4*)g_xlh;   // row = 32 uint4
    const float4* xr4 = (const float4*)g_xr;

    float4 r0 = xr4[(size_t)nidx * 64 + lane * 2];
    float4 r1 = xr4[(size_t)nidx * 64 + lane * 2 + 1];
    float rr[8] = {r0.x, r0.y, r0.z, r0.w, r1.x, r1.y, r1.z, r1.w};
    float4 a0 = ((const float4*)att)[lane * 2];
    float4 a1 = ((const float4*)att)[lane * 2 + 1];
    float at[8] = {a0.x, a0.y, a0.z, a0.w, a1.x, a1.y, a1.z, a1.w};

    float m = -1e30f, s = 0.f;
    float acc[8] = {0.f, 0.f, 0.f, 0.f, 0.f, 0.f, 0.f, 0.f};
    int e0 = valid ? g_rowptr[node] : 0;
    int e1 = valid ? g_rowptr[node + 1] : 0;
    int e = e0;
    for (; e + 2 <= e1; e += 2) {             // 2-edge unroll
        int j0 = g_ssrc[e], j1 = g_ssrc[e + 1];
        uint4 q0 = xlh[(size_t)j0 * 32 + lane];
        uint4 q1 = xlh[(size_t)j1 * 32 + lane];
        float f0[8], f1[8];
        unpack8(q0, f0);
        unpack8(q1, f1);
        float p0 = 0.f, p1 = 0.f;
#pragma unroll
        for (int k = 0; k < 8; k++) {
            float t0 = f0[k] + rr[k];
            float t1 = f1[k] + rr[k];
            t0 = (t0 > 0.f) ? t0 : 0.2f * t0;
            t1 = (t1 > 0.f) ? t1 : 0.2f * t1;
            p0 += at[k] * t0;
            p1 += at[k] * t1;
        }
        p0 += __shfl_xor_sync(0xffffffffu, p0, 1);
        p1 += __shfl_xor_sync(0xffffffffu, p1, 1);
        p0 += __shfl_xor_sync(0xffffffffu, p0, 2);
        p1 += __shfl_xor_sync(0xffffffffu, p1, 2);
        p0 += __shfl_xor_sync(0xffffffffu, p0, 4);
        p1 += __shfl_xor_sync(0xffffffffu, p1, 4);
        float mn = fmaxf(m, fmaxf(p0, p1));
        float sc = __expf(m - mn);
        float w0 = __expf(p0 - mn);
        float w1 = __expf(p1 - mn);
        s = s * sc + w0 + w1;
#pragma unroll
        for (int k = 0; k < 8; k++)
            acc[k] = acc[k] * sc + w0 * f0[k] + w1 * f1[k];
        m = mn;
    }
    if (e < e1) {                             // tail (0 or 1 edge)
        int j = g_ssrc[e];
        uint4 q = xlh[(size_t)j * 32 + lane];
        float f[8];
        unpack8(q, f);
        float p = 0.f;
#pragma unroll
        for (int k = 0; k < 8; k++) {
            float t = f[k] + rr[k];
            t = (t > 0.f) ? t : 0.2f * t;
            p += at[k] * t;
        }
        p += __shfl_xor_sync(0xffffffffu, p, 1);
        p += __shfl_xor_sync(0xffffffffu, p, 2);
        p += __shfl_xor_sync(0xffffffffu, p, 4);
        float mn = fmaxf(m, p);
        float sc = __expf(m - mn);
        float ww = __expf(p - mn);
        s = s * sc + ww;
#pragma unroll
        for (int k = 0; k < 8; k++) acc[k] = acc[k] * sc + ww * f[k];
        m = mn;
    }
    float inv = 1.0f / s;
#pragma unroll
    for (int k = 0; k < 8; k++) {
        float v = acc[k] * inv;                    // per-head normalized
        v += __shfl_xor_sync(0xffffffffu, v, 8);   // sum over 4 heads
        v += __shfl_xor_sync(0xffffffffu, v, 16);
        acc[k] = v;
    }
    if (lane < 8) {
        float4 b0 = ((const float4*)bias)[lane * 2];
        float4 b1 = ((const float4*)bias)[lane * 2 + 1];
        float bv[8] = {b0.x, b0.y, b0.z, b0.w, b1.x, b1.y, b1.z, b1.w};
        float o[8];
#pragma unroll
        for (int k = 0; k < 8; k++) {
            o[k] = valid ? (0.25f * acc[k] + bv[k]) : 0.f;
            ssum[w][lane * 8 + k] = o[k];
            ssq[w][lane * 8 + k] = o[k] * o[k];
        }
        if (valid) {
            float4 w0 = make_float4(o[0], o[1], o[2], o[3]);
            float4 w1 = make_float4(o[4], o[5], o[6], o[7]);
            ((float4*)g_gat)[(size_t)node * 16 + lane * 2]     = w0;
            ((float4*)g_gat)[(size_t)node * 16 + lane * 2 + 1] = w1;
        }
    }
    __syncthreads();
    if (threadIdx.x < 64) {                   // per-block BN partials (fixed order)
        float s2 = 0.f, q2 = 0.f;
#pragma unroll
        for (int ww = 0; ww < 8; ww++) {
            s2 += ssum[ww][threadIdx.x];
            q2 += ssq[ww][threadIdx.x];
        }
        g_ps2[(size_t)blockIdx.x * 64 + threadIdx.x] = s2;
        g_pq2[(size_t)blockIdx.x * 64 + threadIdx.x] = q2;
    }
}

// ---------------- BN finalize: one block per channel, deterministic ---------
__global__ void k_bnfin2(const float* __restrict__ gamma, const float* __restrict__ beta,
                         int N, int nblk) {
    __shared__ float S[256], Q[256];
    int c = blockIdx.x;                       // 64 blocks
    int t = threadIdx.x;                      // 256 threads
    float s = 0.f, q = 0.f;
    for (int b = t; b < nblk; b += 256) {     // fixed per-thread stride order
        s += g_ps2[(size_t)b * 64 + c];
        q += g_pq2[(size_t)b * 64 + c];
    }
    S[t] = s; Q[t] = q;
    __syncthreads();
    for (int off = 128; off > 0; off >>= 1) { // fixed tree order
        if (t < off) { S[t] += S[t + off]; Q[t] += Q[t + off]; }
        __syncthreads();
    }
    if (t == 0) {
        float mu = S[0] / (float)N;
        float var = Q[0] / (float)N - mu * mu;
        float iv = rsqrtf(var + 1e-5f);
        float a = gamma[c] * iv;
        g_bna[c] = a;
        g_bnb[c] = beta[c] - a * mu;
    }
}

__global__ void k_bngelu(int total, int residual) {
    int i = blockIdx.x * blockDim.x + threadIdx.x;
    if (i >= total) return;
    int c = i & 63;
    float t = g_bna[c] * g_gat[i] + g_bnb[c];
    float ge = 0.5f * t * (1.0f + erff(t * 0.70710678118654752f));
    g_h[i] = residual ? (ge + g_h[i]) : ge;
}

// ---------------- pooling + heads -------------------------------------------
__global__ void k_bounds(const int* __restrict__ batch, int N, int G) {
    int i = blockIdx.x * blockDim.x + threadIdx.x;
    if (i >= N) return;
    int b = batch[i];
    int prev = (i == 0) ? -1 : batch[i - 1];
    for (int g = prev + 1; g <= b; g++) g_gstart[g] = i;
    if (i == N - 1) for (int g = b + 1; g <= G; g++) g_gstart[g] = N;
}

__global__ void k_pool(int G) {
    int g = blockIdx.x, c = threadIdx.x;   // 64 threads
    float s = 0.f;
    int e = g_gstart[g + 1];
    for (int n = g_gstart[g]; n < e; n++) s += g_h[(size_t)n * 64 + c];
    g_pool[(size_t)g * 64 + c] = s;
}

__global__ void k_heads(const float* __restrict__ Wmu, const float* __restrict__ bmu,
                        const float* __restrict__ Wlv, const float* __restrict__ blv,
                        float* __restrict__ out, int G) {
    int g = blockIdx.x, t = threadIdx.x;   // 128 threads
    __shared__ float p[64];
    if (t < 64) p[t] = g_pool[(size_t)g * 64 + t];
    __syncthreads();
    int c = t & 63;
    const float* W = (t < 64) ? Wmu : Wlv;
    float s = (t < 64) ? bmu[c] : blv[c];
    for (int k = 0; k < 64; k++) s += p[k] * W[k * 64 + c];
    out[((t < 64) ? 0 : (size_t)G * 64) + (size_t)g * 64 + c] = s;
}

// ---------------- host orchestration ----------------------------------------
extern "C" void kernel_launch(void* const* d_in, const int* in_sizes, int n_in,
                              void* d_out, int out_size) {
    // metadata: x, edge_src, edge_dst, batch, [num_graphs],
    //           (Wl,Wr,att,b,g,be) x3, Wmu, bmu, Wlv, blv
    bool has_ng = (n_in >= 27);
    auto IX = [&](int i) { return has_ng ? i : (i > 4 ? i - 1 : i); };

    const float* x     = (const float*)d_in[0];
    const int*   esrc  = (const int*)d_in[1];
    const int*   edst  = (const int*)d_in[2];
    const int*   batch = (const int*)d_in[3];

    int N  = in_sizes[0] / 64;
    int E  = in_sizes[1];
    int EA = E + N;
    int G  = out_size / 128;   // 2 * G * 64

    void* hptr_v = nullptr;
    cudaGetSymbolAddress(&hptr_v, g_h);
    const float* hbuf = (const float*)hptr_v;

    // ---- deterministic CSR: bucket scatter + per-bucket index sort ----
    // (g_deg statically zero at load; k_place re-zeroes it each execution)
    k_deg        <<<(EA + 255) / 256, 256>>>(edst, E, EA);
    k_scan       <<<1, 1024>>>(N, EA);
    k_place      <<<(EA + 255) / 256, 256>>>(edst, E, EA, N);
    k_sortbuckets<<<(N + 127) / 128, 128>>>(esrc, E, N);

    // ---- 3 GATv2 layers ----
    int gatblk = (N + 7) / 8;
    const float* hin = x;
    for (int L = 0; L < 3; L++) {
        int b0 = 5 + 6 * L;
        const float* Wl  = (const float*)d_in[IX(b0 + 0)];
        const float* Wr  = (const float*)d_in[IX(b0 + 1)];
        const float* att = (const float*)d_in[IX(b0 + 2)];
        const float* bb  = (const float*)d_in[IX(b0 + 3)];
        const float* gg  = (const float*)d_in[IX(b0 + 4)];
        const float* be  = (const float*)d_in[IX(b0 + 5)];

        dim3 gg_gemm((N + 127) / 128, 8);
        k_gemm  <<<gg_gemm, 256>>>(hin, Wl, Wr, N);
        k_gat   <<<gatblk, 256>>>(att, bb, N);
        k_bnfin2<<<64, 256>>>(gg, be, N, gatblk);
        k_bngelu<<<(N * 64 + 255) / 256, 256>>>(N * 64, (L > 0) ? 1 : 0);
        hin = hbuf;
    }

    // ---- pool + heads ----
    const float* Wmu = (const float*)d_in[IX(23)];
    const float* bmu = (const float*)d_in[IX(24)];
    const float* Wlv = (const float*)d_in[IX(25)];
    const float* blv = (const float*)d_in[IX(26)];

    k_bounds<<<(N + 255) / 256, 256>>>(batch, N, G);
    k_pool  <<<G, 64>>>(G);
    k_heads <<<G, 128>>>(Wmu, bmu, Wlv, blv, (float*)d_out, G);
}